// round 14
// baseline (speedup 1.0000x reference)
#include <cuda_runtime.h>
#include <cuda_fp16.h>

#define NB   32
#define NT   512
#define ND   768
#define NK   256
#define NKP1 257
#define NH   512
#define NP   769          // NKP1 + NH
#define NCTA 128
#define NPACK (128*769*16)

// ---------------- device scratch (static; no cudaMalloc allowed) ----------
__device__ float g_S[(size_t)NB*NT*NT];    // gram -> (in place) softmax weights
__device__ float g_wc[NB*NT];              // precomputed confidence readout
__device__ float g_Wpack[NPACK];           // per-CTA packed LSTM weights
__device__ float g_hT[NH*NB];              // h, layout [j][b]
__device__ float g_hB[NB*NH];              // h, layout [b][j]
__device__ float g_keyrT[NKP1*NB];         // key_r, layout [k][b]
__device__ __align__(128) unsigned g_cnt[32];  // arrival counter (own line)
__device__ __align__(128) unsigned g_rel[32];  // release generation (own line)

__device__ __forceinline__ float sigmf(float x) { return 1.f / (1.f + __expf(-x)); }
__device__ __forceinline__ float tanhfast(float x) {
    return 2.f / (1.f + __expf(-2.f * x)) - 1.f;
}

__device__ __forceinline__ void fma2(unsigned long long &acc, unsigned long long a,
                                     unsigned long long w) {
    asm("fma.rn.f32x2 %0, %1, %2, %0;" : "+l"(acc) : "l"(a), "l"(w));
}

__device__ __forceinline__ void cp_async16(void* smem_dst, const void* gsrc) {
    unsigned s = (unsigned)__cvta_generic_to_shared(smem_dst);
    asm volatile("cp.async.cg.shared.global [%0], [%1], 16;" :: "r"(s), "l"(gsrc));
}

// counter barrier: 1 atomic per CTA on arrive, 1 polling thread per CTA on wait.
// g_cnt and g_rel on separate 128-B lines so arrivals don't disturb polls.
__device__ __forceinline__ void bar_arrive(unsigned gen) {
    __syncthreads();
    if (threadIdx.x == 0) {
        unsigned arr;
        asm volatile("atom.add.acq_rel.gpu.global.u32 %0, [%1], 1;"
                     : "=r"(arr) : "l"(&g_cnt[0]) : "memory");
        if (arr + 1u == gen * (unsigned)NCTA)
            asm volatile("st.release.gpu.global.u32 [%0], %1;"
                         :: "l"(&g_rel[0]), "r"(gen) : "memory");
    }
}
__device__ __forceinline__ void bar_wait(unsigned gen) {
    if (threadIdx.x == 0) {
        unsigned v;
        do {
            asm volatile("ld.relaxed.gpu.global.u32 %0, [%1];"
                         : "=r"(v) : "l"(&g_rel[0]) : "memory");
        } while (v < gen);
        asm volatile("ld.acquire.gpu.global.u32 %0, [%1];"
                     : "=r"(v) : "l"(&g_rel[0]) : "memory");
    }
    __syncthreads();
}

// ---------------- weight pack + state/flag init ----------------------------
__global__ void k_pack(const float* __restrict__ Wx, const float* __restrict__ Wh) {
    int idx = blockIdx.x * blockDim.x + threadIdx.x;
    if (idx < NKP1*NB) g_keyrT[idx] = 0.f;
    if (idx < 32) { g_cnt[idx] = 0u; g_rel[idx] = 0u; }
    if (idx >= NPACK) return;
    int cl = idx & 15;
    int r  = idx >> 4;
    int p  = r % NP;
    int ct = r / NP;
    int jj = cl & 3, gate = cl >> 2;
    int col = gate * NH + ct * 4 + jj;
    float v = (p < NKP1) ? Wx[(size_t)p * 2048 + col]
                         : Wh[(size_t)(p - NKP1) * 2048 + col];
    g_Wpack[idx] = v;
}

// ---------------- gram: transposed tiles + f32x2 FMA -----------------------
__global__ void k_gram(const float* __restrict__ x) {
    __shared__ float sat[16][68];
    __shared__ float sbt[16][68];
    int bx = blockIdx.x;
    int b = bx / 36, pr = bx % 36;
    int ti = 0;
    while ((ti + 1) * (ti + 2) / 2 <= pr) ti++;
    int tj = pr - ti * (ti + 1) / 2;
    int tid = threadIdx.x;
    int ry = tid >> 4, rx = tid & 15;
    unsigned long long acc2g[4][2];
#pragma unroll
    for (int i = 0; i < 4; i++) { acc2g[i][0] = 0ull; acc2g[i][1] = 0ull; }
    const float* xa = x + ((size_t)b * NT + ti * 64) * ND;
    const float* xb = x + ((size_t)b * NT + tj * 64) * ND;
    for (int d0 = 0; d0 < ND; d0 += 16) {
        __syncthreads();
#pragma unroll
        for (int k = 0; k < 4; ++k) {
            int idx = tid + k * 256;
            int r = idx >> 4, c = idx & 15;
            sat[c][r] = xa[(size_t)r * ND + d0 + c];
            sbt[c][r] = xb[(size_t)r * ND + d0 + c];
        }
        __syncthreads();
#pragma unroll
        for (int dd = 0; dd < 16; ++dd) {
            float4 a4 = *(const float4*)&sat[dd][ry * 4];
            float4 b4 = *(const float4*)&sbt[dd][rx * 4];
            unsigned long long bp0, bp1;
            asm("mov.b64 %0, {%1, %2};" : "=l"(bp0)
                : "r"(__float_as_uint(b4.x)), "r"(__float_as_uint(b4.y)));
            asm("mov.b64 %0, {%1, %2};" : "=l"(bp1)
                : "r"(__float_as_uint(b4.z)), "r"(__float_as_uint(b4.w)));
            float av[4] = {a4.x, a4.y, a4.z, a4.w};
#pragma unroll
            for (int i = 0; i < 4; i++) {
                unsigned long long ad;
                asm("mov.b64 %0, {%1, %1};" : "=l"(ad) : "r"(__float_as_uint(av[i])));
                fma2(acc2g[i][0], bp0, ad);
                fma2(acc2g[i][1], bp1, ad);
            }
        }
    }
#pragma unroll
    for (int i = 0; i < 4; i++) {
        int row = ti * 64 + ry * 4 + i;
        float f0, f1, f2, f3;
        asm("mov.b64 {%0, %1}, %2;" : "=f"(f0), "=f"(f1) : "l"(acc2g[i][0]));
        asm("mov.b64 {%0, %1}, %2;" : "=f"(f2), "=f"(f3) : "l"(acc2g[i][1]));
        float4* dst = (float4*)&g_S[((size_t)b * NT + row) * NT + tj * 64 + rx * 4];
        *dst = make_float4(f0, f1, f2, f3);
    }
}

// ---------------- row softmax over t' < t, + wc ----------------------------
__global__ void k_softmax(const float* __restrict__ cgain, const float* __restrict__ cbias) {
    int bx = blockIdx.x;
    int t = bx & (NT - 1), b = bx >> 9;
    int tid = threadIdx.x;
    if (t == 0) { if (tid == 0) g_wc[b * NT] = 0.f; return; }
    float* row = &g_S[((size_t)b * NT + t) * NT];
    __shared__ float sred[4];
    __shared__ float sbuf[NT];
    float gain = cgain[0], bias = cbias[0];

    float m = -3.4e38f;
    for (int i = tid; i < t; i += 128) m = fmaxf(m, row[i]);
#pragma unroll
    for (int o = 16; o; o >>= 1) m = fmaxf(m, __shfl_xor_sync(~0u, m, o));
    if ((tid & 31) == 0) sred[tid >> 5] = m;
    __syncthreads();
    m = fmaxf(fmaxf(sred[0], sred[1]), fmaxf(sred[2], sred[3]));

    float s = 0.f;
    for (int i = tid; i < t; i += 128) { float e = __expf(row[i] - m); sbuf[i] = e; s += e; }
#pragma unroll
    for (int o = 16; o; o >>= 1) s += __shfl_xor_sync(~0u, s, o);
    __syncthreads();
    if ((tid & 31) == 0) sred[tid >> 5] = s;
    __syncthreads();
    s = sred[0] + sred[1] + sred[2] + sred[3];
    float inv = 1.f / s;

    float wca = 0.f;
    for (int i = tid; i < t; i += 128) {
        float sim = row[i];
        float w = sbuf[i] * inv;
        row[i] = w;
        wca += w * sigmf(sim * gain + bias);
    }
#pragma unroll
    for (int o = 16; o; o >>= 1) wca += __shfl_xor_sync(~0u, wca, o);
    __syncthreads();
    if ((tid & 31) == 0) sred[tid >> 5] = wca;
    __syncthreads();
    if (tid == 0) g_wc[b * NT + t] = sred[0] + sred[1] + sred[2] + sred[3];
}

// ---------------- persistent recurrence kernel -----------------------------
#define SM_SACT 24608
#define SM_RED  8736
#define SM_ZBUF 528
#define SM_PH2  1924
#define SM_FLOATS (SM_SACT + SM_RED + 2*SM_ZBUF + SM_PH2 + 16384)

__global__ void __launch_bounds__(256, 1) k_rec(
    const float* __restrict__ b_lstm, const float* __restrict__ W_key,
    const float* __restrict__ b_key,  const float* __restrict__ W_g,
    const float* __restrict__ b_g,    float* __restrict__ out)
{
    extern __shared__ float sm[];
    float* sAct  = sm;
    float* red   = sm + SM_SACT;
    float* zbuf  = red + SM_RED;
    float* zbufH = zbuf + SM_ZBUF;
    float* sh    = zbufH + SM_ZBUF;
    float* sWrow = sh + 512;
    float* redk  = sWrow + 512;
    __half* sMk  = (__half*)(redk + 900);       // [t'][64] fp16, CTA-private

    const int ct = blockIdx.x, tid = threadIdx.x;
    const int cl = tid & 15, chunk = tid >> 4;
    const int qrot = (chunk & 1) << 2;          // bank-conflict breaker
    const float* wp = g_Wpack + ((size_t)ct * NP) * 16 + cl;
    const int j0 = ct * 4;
    const int b2 = ct >> 2, kq = ct & 3, k0 = kq * 64;
    const int kl = tid & 63, qq = tid >> 6;
    const int kp = tid & 31, q8 = tid >> 5;     // attention 8-way split
    float creg = 0.f;

    // ---- weights + small params register-resident for all 512 steps
    float wx[16];
#pragma unroll
    for (int i = 0; i < 16; ++i) wx[i] = __ldg(&wp[(size_t)(chunk * 16 + i) * 16]);
    const float wxe = (chunk == 15) ? __ldg(&wp[(size_t)256 * 16]) : 0.f;
    float wh[32];
#pragma unroll
    for (int i = 0; i < 32; ++i) wh[i] = __ldg(&wp[(size_t)(NKP1 + chunk * 32 + i) * 16]);
    unsigned wk2[64];
    {
        const float* wkp = W_key + (size_t)(qq * 128) * NK + k0 + kl;
#pragma unroll
        for (int i = 0; i < 64; ++i) {
            float w0 = __ldg(&wkp[(size_t)(2 * i) * NK]);
            float w1 = __ldg(&wkp[(size_t)(2 * i + 1) * NK]);
            __half2 h2 = __floats2half2_rn(w0, w1);
            wk2[i] = *(unsigned*)&h2;
        }
    }
    const float wg0 = __ldg(&W_g[tid]), wg1 = __ldg(&W_g[tid + 256]);
    const float bgr = __ldg(&b_g[0]);
    const float bk  = (tid < 64) ? __ldg(&b_key[k0 + tid]) : 0.f;
    const int c0 = tid >> 5, c1 = (tid + 256) >> 5;
    const float bl0 = __ldg(&b_lstm[(c0 >> 2) * NH + j0 + (c0 & 3)]);
    const float bl1 = __ldg(&b_lstm[(c1 >> 2) * NH + j0 + (c1 & 3)]);

    for (int t = 0; t < NT; ++t) {
        // ==== S0: wait key_r(t-1) exchange =================================
        if (t > 0) bar_wait(2u * t);
        const float wcv = __ldg(&g_wc[b2 * NT + t]);
        // ==== S1: issue key_r staging (covered by WhB below) ===============
        {
            const float4* s1 = (const float4*)g_keyrT;
            float4* d1 = (float4*)sAct;
            for (int i = tid; i < 2056; i += 256) cp_async16(d1 + i, s1 + i);
            asm volatile("cp.async.commit_group;" ::: "memory");
        }
        // ==== S2: WhB — all 32 rows, batch-groups 4..7 =====================
        if (t > 0) {
            unsigned long long accH[8];
#pragma unroll
            for (int i = 0; i < 8; i++) accH[i] = 0ull;
#pragma unroll
            for (int i = 0; i < 32; ++i) {
                unsigned long long w2;
                asm("mov.b64 %0, {%1, %1};" : "=l"(w2) : "r"(__float_as_uint(wh[i])));
                const ulonglong2* a4 = (const ulonglong2*)(sAct + (NKP1 + chunk * 32 + i) * 32);
#pragma unroll
                for (int q = 0; q < 4; ++q) {
                    ulonglong2 aa = a4[(q + 4 + qrot) & 7];
                    fma2(accH[2 * q],     aa.x, w2);
                    fma2(accH[2 * q + 1], aa.y, w2);
                }
            }
#pragma unroll
            for (int q = 0; q < 4; ++q) {
                int bb = ((q + 4 + qrot) & 7) * 4;
                float f0, f1, f2, f3;
                asm("mov.b64 {%0, %1}, %2;" : "=f"(f0), "=f"(f1) : "l"(accH[2 * q]));
                asm("mov.b64 {%0, %1}, %2;" : "=f"(f2), "=f"(f3) : "l"(accH[2 * q + 1]));
                red[(bb + 0) * 273 + cl * 17 + chunk] = f0;
                red[(bb + 1) * 273 + cl * 17 + chunk] = f1;
                red[(bb + 2) * 273 + cl * 17 + chunk] = f2;
                red[(bb + 3) * 273 + cl * 17 + chunk] = f3;
            }
        }
        __syncthreads();
        // ==== S3: reduce Wh partials -> zbufH ==============================
        if (t > 0) {
            for (int o = tid; o < 512; o += 256) {
                int c = o >> 5, b = o & 31;
                const float* rr = &red[b * 273 + c * 17];
                float s = 0.f;
#pragma unroll
                for (int ch = 0; ch < 16; ++ch) s += rr[ch];
                zbufH[c * 33 + b] = s;
            }
        } else {
            for (int i = tid; i < SM_ZBUF; i += 256) zbufH[i] = 0.f;
        }
        asm volatile("cp.async.wait_group 0;" ::: "memory");
        __syncthreads();
        // ==== S4: W_x GEMM =================================================
        unsigned long long acc2[16];
#pragma unroll
        for (int i = 0; i < 16; i++) acc2[i] = 0ull;
#pragma unroll
        for (int i = 0; i < 16; ++i) {
            unsigned long long w2;
            asm("mov.b64 %0, {%1, %1};" : "=l"(w2) : "r"(__float_as_uint(wx[i])));
            const ulonglong2* a4 = (const ulonglong2*)(sAct + (chunk * 16 + i) * 32);
#pragma unroll
            for (int q = 0; q < 8; ++q) {
                ulonglong2 aa = a4[(q + qrot) & 7];
                fma2(acc2[2 * q],     aa.x, w2);
                fma2(acc2[2 * q + 1], aa.y, w2);
            }
        }
        if (chunk == 15) {
            unsigned long long w2;
            asm("mov.b64 %0, {%1, %1};" : "=l"(w2) : "r"(__float_as_uint(wxe)));
            const ulonglong2* a4 = (const ulonglong2*)(sAct + 256 * 32);
#pragma unroll
            for (int q = 0; q < 8; ++q) {
                ulonglong2 aa = a4[(q + qrot) & 7];
                fma2(acc2[2 * q],     aa.x, w2);
                fma2(acc2[2 * q + 1], aa.y, w2);
            }
        }
#pragma unroll
        for (int q = 0; q < 8; ++q) {
            int bb = ((q + qrot) & 7) * 4;
            float f0, f1, f2, f3;
            asm("mov.b64 {%0, %1}, %2;" : "=f"(f0), "=f"(f1) : "l"(acc2[2 * q]));
            asm("mov.b64 {%0, %1}, %2;" : "=f"(f2), "=f"(f3) : "l"(acc2[2 * q + 1]));
            red[(bb + 0) * 273 + cl * 17 + chunk] = f0;
            red[(bb + 1) * 273 + cl * 17 + chunk] = f1;
            red[(bb + 2) * 273 + cl * 17 + chunk] = f2;
            red[(bb + 3) * 273 + cl * 17 + chunk] = f3;
        }
        __syncthreads();
        { // combine: Wx partials + carried Wh + bias (preloaded)
            int b = tid & 31;
            const float* rr = &red[b * 273 + c0 * 17];
            float s = 0.f;
#pragma unroll
            for (int ch = 0; ch < 16; ++ch) s += rr[ch];
            zbuf[c0 * 33 + b] = s + zbufH[c0 * 33 + b] + bl0;
            rr = &red[b * 273 + c1 * 17];
            s = 0.f;
#pragma unroll
            for (int ch = 0; ch < 16; ++ch) s += rr[ch];
            zbuf[c1 * 33 + b] = s + zbufH[c1 * 33 + b] + bl1;
        }
        __syncthreads();
        // ==== S5: gates; c-state register-resident =========================
        if (tid < 128) {
            int jj = tid >> 5, b = tid & 31;
            float zi = zbuf[(0 + jj) * 33 + b];
            float zf = zbuf[(4 + jj) * 33 + b];
            float zc = zbuf[(8 + jj) * 33 + b];
            float zo = zbuf[(12 + jj) * 33 + b];
            float ig = sigmf(zi), fg = sigmf(zf);
            float gc = tanhfast(zc), og = sigmf(zo);
            creg = fg * creg + ig * gc;
            float hv = og * tanhfast(creg);
            int j = j0 + jj;
            if (t == NT - 1) {
                out[b * NH + j] = hv;
            } else {
                __stcg(&g_hT[j * NB + b], hv);
                __stcg(&g_hB[b * NH + j], hv);
            }
        }
        if (t == NT - 1) break;
        bar_arrive(2u * t + 1u);
        // ==== S7: attention partials (CTA-local) fill bar1 gap =============
        {
            float ax0 = 0.f, ay0 = 0.f, ax1 = 0.f, ay1 = 0.f;
            const __half2* mk2 = ((const __half2*)sMk) + kp;
            int t2 = q8;
            for (; t2 + 8 < t; t2 += 16) {
                float w0 = sWrow[t2], w1 = sWrow[t2 + 8];
                float2 m0 = __half22float2(mk2[t2 * 32]);
                float2 m1 = __half22float2(mk2[(t2 + 8) * 32]);
                ax0 += w0 * m0.x; ay0 += w0 * m0.y;
                ax1 += w1 * m1.x; ay1 += w1 * m1.y;
            }
            for (; t2 < t; t2 += 8) {
                float w0 = sWrow[t2];
                float2 m0 = __half22float2(mk2[t2 * 32]);
                ax0 += w0 * m0.x; ay0 += w0 * m0.y;
            }
            redk[384 + (kp * 8 + q8) * 2]     = ax0 + ax1;
            redk[384 + (kp * 8 + q8) * 2 + 1] = ay0 + ay1;
        }
        bar_wait(2u * t + 1u);
        // ==== S9: async loads: hB | S row t+1 | h stage ====================
        if (tid < 128)
            cp_async16(((float4*)sh) + tid,
                       ((const float4*)(g_hB + (size_t)b2 * NH)) + tid);
        asm volatile("cp.async.commit_group;" ::: "memory");
        if (tid < 128)
            cp_async16(((float4*)sWrow) + tid,
                       ((const float4*)&g_S[((size_t)b2 * NT + t + 1) * NT]) + tid);
        asm volatile("cp.async.commit_group;" ::: "memory");
        {
            const float4* s2 = (const float4*)g_hT;
            float4* d2 = ((float4*)sAct) + 2056;
            for (int i = tid; i < 4096; i += 256) cp_async16(d2 + i, s2 + i);
            asm volatile("cp.async.commit_group;" ::: "memory");
        }
        // combine attention partials into registers while loads fly
        float attns = 0.f;
        if (tid < 64) {
            int kpp = tid >> 1, parr = tid & 1;
#pragma unroll
            for (int q = 0; q < 8; ++q) attns += redk[384 + (kpp * 8 + q) * 2 + parr];
        }
        asm volatile("cp.async.wait_group 2;" ::: "memory");  // hB done
        __syncthreads();
        // ==== S10: g, key_w, sMk[t], key_r — single sync ===================
        float pg = sh[tid] * wg0 + sh[tid + 256] * wg1;
#pragma unroll
        for (int o = 16; o; o >>= 1) pg += __shfl_xor_sync(~0u, pg, o);
        if ((tid & 31) == 0) redk[328 + (tid >> 5)] = pg;
        float ka[4] = {0.f, 0.f, 0.f, 0.f};
        {
            const float4* shq4 = (const float4*)(sh + qq * 128);
#pragma unroll
            for (int i = 0; i < 32; ++i) {
                float4 h4 = shq4[i];
                float2 f0 = __half22float2(*(__half2*)&wk2[2 * i]);
                float2 f1 = __half22float2(*(__half2*)&wk2[2 * i + 1]);
                ka[0] += h4.x * f0.x;
                ka[1] += h4.y * f0.y;
                ka[2] += h4.z * f1.x;
                ka[3] += h4.w * f1.y;
            }
        }
        redk[kl * 5 + qq] = (ka[0] + ka[1]) + (ka[2] + ka[3]);
        __syncthreads();
        float gv;
        {
            float gs = ((redk[328] + redk[329]) + (redk[330] + redk[331]))
                     + ((redk[332] + redk[333]) + (redk[334] + redk[335]));
            gv = sigmf(gs + bgr);
        }
        if (tid < 64) {
            float kw = redk[tid * 5] + redk[tid * 5 + 1] + redk[tid * 5 + 2]
                     + redk[tid * 5 + 3] + bk;
            sMk[t * 64 + tid] = __float2half_rn(kw);
            float kr = (t > 0) ? gv * attns : 0.f;
            __stcg(&g_keyrT[(k0 + tid) * NB + b2], kr);
        }
        if (tid == 64 && kq == 0) {
            float kr = (t > 0) ? gv * wcv : 0.f;
            __stcg(&g_keyrT[NK * NB + b2], kr);
        }
        bar_arrive(2u * t + 2u);
        // ==== S12: WhA — all 32 rows, batch-groups 0..3 ====================
        asm volatile("cp.async.wait_group 0;" ::: "memory");
        __syncthreads();
        {
            unsigned long long accH[8];
#pragma unroll
            for (int i = 0; i < 8; i++) accH[i] = 0ull;
#pragma unroll
            for (int i = 0; i < 32; ++i) {
                unsigned long long w2;
                asm("mov.b64 %0, {%1, %1};" : "=l"(w2) : "r"(__float_as_uint(wh[i])));
                const ulonglong2* a4 = (const ulonglong2*)(sAct + (NKP1 + chunk * 32 + i) * 32);
#pragma unroll
                for (int q = 0; q < 4; ++q) {
                    ulonglong2 aa = a4[(q + qrot) & 7];
                    fma2(accH[2 * q],     aa.x, w2);
                    fma2(accH[2 * q + 1], aa.y, w2);
                }
            }
#pragma unroll
            for (int q = 0; q < 4; ++q) {
                int bb = ((q + qrot) & 7) * 4;
                float f0, f1, f2, f3;
                asm("mov.b64 {%0, %1}, %2;" : "=f"(f0), "=f"(f1) : "l"(accH[2 * q]));
                asm("mov.b64 {%0, %1}, %2;" : "=f"(f2), "=f"(f3) : "l"(accH[2 * q + 1]));
                red[(bb + 0) * 273 + cl * 17 + chunk] = f0;
                red[(bb + 1) * 273 + cl * 17 + chunk] = f1;
                red[(bb + 2) * 273 + cl * 17 + chunk] = f2;
                red[(bb + 3) * 273 + cl * 17 + chunk] = f3;
            }
        }
        // batch-groups 4..7 computed at next iteration's S2 (covers key_r load)
    }
}

// ---------------- launch ---------------------------------------------------
extern "C" void kernel_launch(void* const* d_in, const int* in_sizes, int n_in,
                              void* d_out, int out_size) {
    const float* x      = (const float*)d_in[0];
    const float* W_x    = (const float*)d_in[1];
    const float* W_h    = (const float*)d_in[2];
    const float* b_lstm = (const float*)d_in[3];
    const float* W_key  = (const float*)d_in[4];
    const float* b_key  = (const float*)d_in[5];
    const float* W_g    = (const float*)d_in[6];
    const float* b_g    = (const float*)d_in[7];
    float* out = (float*)d_out;

    cudaFuncSetAttribute(k_rec, cudaFuncAttributeMaxDynamicSharedMemorySize,
                         SM_FLOATS * (int)sizeof(float));

    k_pack<<<(NPACK + 255) / 256, 256>>>(W_x, W_h);
    k_gram<<<NB * 36, 256>>>(x);
    k_softmax<<<NB * NT, 128>>>((const float*)d_in[8], (const float*)d_in[9]);
    k_rec<<<NCTA, 256, SM_FLOATS * (int)sizeof(float)>>>(b_lstm, W_key, b_key, W_g, b_g, out);
}

// round 15
// speedup vs baseline: 1.2168x; 1.2168x over previous
#include <cuda_runtime.h>
#include <cuda_fp16.h>

#define NB   32
#define NT   512
#define ND   768
#define NK   256
#define NKP1 257
#define NH   512
#define NP   769          // NKP1 + NH
#define NCTA 128
#define NPACK (128*769*16)

// ---------------- device scratch (static; no cudaMalloc allowed) ----------
__device__ float g_S[(size_t)NB*NT*NT];    // gram -> (in place) softmax weights
__device__ float g_wc[NB*NT];              // precomputed confidence readout
__device__ float g_Wpack[NPACK];           // per-CTA packed LSTM weights
__device__ float g_hT[NH*NB];              // h, layout [j][b]
__device__ float g_hB[NB*NH];              // h, layout [b][j]
__device__ float g_keyrT[NKP1*NB];         // key_r, layout [k][b]
__device__ unsigned g_arr[NCTA*32];        // barrier flags, one 128B line each

__device__ __forceinline__ float sigmf(float x) { return 1.f / (1.f + __expf(-x)); }
__device__ __forceinline__ float tanhfast(float x) {
    return 2.f / (1.f + __expf(-2.f * x)) - 1.f;
}

__device__ __forceinline__ void fma2(unsigned long long &acc, unsigned long long a,
                                     unsigned long long w) {
    asm("fma.rn.f32x2 %0, %1, %2, %0;" : "+l"(acc) : "l"(a), "l"(w));
}

__device__ __forceinline__ void cp_async16(void* smem_dst, const void* gsrc) {
    unsigned s = (unsigned)__cvta_generic_to_shared(smem_dst);
    asm volatile("cp.async.cg.shared.global [%0], [%1], 16;" :: "r"(s), "l"(gsrc));
}

// split-phase grid barrier; each flag on its own 128-B line (proven best)
__device__ __forceinline__ void bar_arrive(unsigned gen) {
    __syncthreads();
    if (threadIdx.x == 0)
        asm volatile("st.release.gpu.u32 [%0], %1;"
                     :: "l"(&g_arr[blockIdx.x * 32]), "r"(gen) : "memory");
}
__device__ __forceinline__ void bar_wait(unsigned gen) {
    if (threadIdx.x < NCTA) {
        unsigned v;
        asm volatile("ld.acquire.gpu.u32 %0, [%1];"
                     : "=r"(v) : "l"(&g_arr[threadIdx.x * 32]) : "memory");
        while (v < gen) {
            __nanosleep(32);
            asm volatile("ld.acquire.gpu.u32 %0, [%1];"
                         : "=r"(v) : "l"(&g_arr[threadIdx.x * 32]) : "memory");
        }
    }
    __syncthreads();
}

// ---------------- weight pack + state/flag init ----------------------------
__global__ void k_pack(const float* __restrict__ Wx, const float* __restrict__ Wh) {
    int idx = blockIdx.x * blockDim.x + threadIdx.x;
    if (idx < NKP1*NB) g_keyrT[idx] = 0.f;
    if (idx < NCTA*32) g_arr[idx] = 0u;
    if (idx >= NPACK) return;
    int cl = idx & 15;
    int r  = idx >> 4;
    int p  = r % NP;
    int ct = r / NP;
    int jj = cl & 3, gate = cl >> 2;
    int col = gate * NH + ct * 4 + jj;
    float v = (p < NKP1) ? Wx[(size_t)p * 2048 + col]
                         : Wh[(size_t)(p - NKP1) * 2048 + col];
    g_Wpack[idx] = v;
}

// ---------------- gram: transposed tiles + f32x2 FMA -----------------------
__global__ void k_gram(const float* __restrict__ x) {
    __shared__ float sat[16][68];
    __shared__ float sbt[16][68];
    int bx = blockIdx.x;
    int b = bx / 36, pr = bx % 36;
    int ti = 0;
    while ((ti + 1) * (ti + 2) / 2 <= pr) ti++;
    int tj = pr - ti * (ti + 1) / 2;
    int tid = threadIdx.x;
    int ry = tid >> 4, rx = tid & 15;
    unsigned long long acc2g[4][2];
#pragma unroll
    for (int i = 0; i < 4; i++) { acc2g[i][0] = 0ull; acc2g[i][1] = 0ull; }
    const float* xa = x + ((size_t)b * NT + ti * 64) * ND;
    const float* xb = x + ((size_t)b * NT + tj * 64) * ND;
    for (int d0 = 0; d0 < ND; d0 += 16) {
        __syncthreads();
#pragma unroll
        for (int k = 0; k < 4; ++k) {
            int idx = tid + k * 256;
            int r = idx >> 4, c = idx & 15;
            sat[c][r] = xa[(size_t)r * ND + d0 + c];
            sbt[c][r] = xb[(size_t)r * ND + d0 + c];
        }
        __syncthreads();
#pragma unroll
        for (int dd = 0; dd < 16; ++dd) {
            float4 a4 = *(const float4*)&sat[dd][ry * 4];
            float4 b4 = *(const float4*)&sbt[dd][rx * 4];
            unsigned long long bp0, bp1;
            asm("mov.b64 %0, {%1, %2};" : "=l"(bp0)
                : "r"(__float_as_uint(b4.x)), "r"(__float_as_uint(b4.y)));
            asm("mov.b64 %0, {%1, %2};" : "=l"(bp1)
                : "r"(__float_as_uint(b4.z)), "r"(__float_as_uint(b4.w)));
            float av[4] = {a4.x, a4.y, a4.z, a4.w};
#pragma unroll
            for (int i = 0; i < 4; i++) {
                unsigned long long ad;
                asm("mov.b64 %0, {%1, %1};" : "=l"(ad) : "r"(__float_as_uint(av[i])));
                fma2(acc2g[i][0], bp0, ad);
                fma2(acc2g[i][1], bp1, ad);
            }
        }
    }
#pragma unroll
    for (int i = 0; i < 4; i++) {
        int row = ti * 64 + ry * 4 + i;
        float f0, f1, f2, f3;
        asm("mov.b64 {%0, %1}, %2;" : "=f"(f0), "=f"(f1) : "l"(acc2g[i][0]));
        asm("mov.b64 {%0, %1}, %2;" : "=f"(f2), "=f"(f3) : "l"(acc2g[i][1]));
        float4* dst = (float4*)&g_S[((size_t)b * NT + row) * NT + tj * 64 + rx * 4];
        *dst = make_float4(f0, f1, f2, f3);
    }
}

// ---------------- row softmax over t' < t, + wc ----------------------------
__global__ void k_softmax(const float* __restrict__ cgain, const float* __restrict__ cbias) {
    int bx = blockIdx.x;
    int t = bx & (NT - 1), b = bx >> 9;
    int tid = threadIdx.x;
    if (t == 0) { if (tid == 0) g_wc[b * NT] = 0.f; return; }
    float* row = &g_S[((size_t)b * NT + t) * NT];
    __shared__ float sred[4];
    __shared__ float sbuf[NT];
    float gain = cgain[0], bias = cbias[0];

    float m = -3.4e38f;
    for (int i = tid; i < t; i += 128) m = fmaxf(m, row[i]);
#pragma unroll
    for (int o = 16; o; o >>= 1) m = fmaxf(m, __shfl_xor_sync(~0u, m, o));
    if ((tid & 31) == 0) sred[tid >> 5] = m;
    __syncthreads();
    m = fmaxf(fmaxf(sred[0], sred[1]), fmaxf(sred[2], sred[3]));

    float s = 0.f;
    for (int i = tid; i < t; i += 128) { float e = __expf(row[i] - m); sbuf[i] = e; s += e; }
#pragma unroll
    for (int o = 16; o; o >>= 1) s += __shfl_xor_sync(~0u, s, o);
    __syncthreads();
    if ((tid & 31) == 0) sred[tid >> 5] = s;
    __syncthreads();
    s = sred[0] + sred[1] + sred[2] + sred[3];
    float inv = 1.f / s;

    float wca = 0.f;
    for (int i = tid; i < t; i += 128) {
        float sim = row[i];
        float w = sbuf[i] * inv;
        row[i] = w;
        wca += w * sigmf(sim * gain + bias);
    }
#pragma unroll
    for (int o = 16; o; o >>= 1) wca += __shfl_xor_sync(~0u, wca, o);
    __syncthreads();
    if ((tid & 31) == 0) sred[tid >> 5] = wca;
    __syncthreads();
    if (tid == 0) g_wc[b * NT + t] = sred[0] + sred[1] + sred[2] + sred[3];
}

// ---------------- persistent recurrence kernel -----------------------------
#define SM_SACT 24608
#define SM_RED  8736
#define SM_ZBUF 528
#define SM_PH2  1924
#define SM_FLOATS (SM_SACT + SM_RED + 2*SM_ZBUF + SM_PH2 + 16384)

__global__ void __launch_bounds__(256, 1) k_rec(
    const float* __restrict__ b_lstm, const float* __restrict__ W_key,
    const float* __restrict__ b_key,  const float* __restrict__ W_g,
    const float* __restrict__ b_g,    float* __restrict__ out)
{
    extern __shared__ float sm[];
    float* sAct  = sm;
    float* red   = sm + SM_SACT;
    float* zbuf  = red + SM_RED;
    float* zbufH = zbuf + SM_ZBUF;
    float* sh    = zbufH + SM_ZBUF;
    float* sWrow = sh + 512;
    float* redk  = sWrow + 512;
    __half* sMk  = (__half*)(redk + 900);       // [t'][64] fp16, CTA-private

    const int ct = blockIdx.x, tid = threadIdx.x;
    const int cl = tid & 15, chunk = tid >> 4;
    const int qrot = (chunk & 1) << 2;          // bank-conflict breaker
    const float* wp = g_Wpack + ((size_t)ct * NP) * 16 + cl;
    const int j0 = ct * 4;
    const int b2 = ct >> 2, kq = ct & 3, k0 = kq * 64;
    const int kl = tid & 63, qq = tid >> 6;
    const int kp = tid & 31, q8 = tid >> 5;     // attention 8-way split
    float creg = 0.f;

    // ---- weights + small params register-resident for all 512 steps
    float wx[16];
#pragma unroll
    for (int i = 0; i < 16; ++i) wx[i] = __ldg(&wp[(size_t)(chunk * 16 + i) * 16]);
    const float wxe = (chunk == 15) ? __ldg(&wp[(size_t)256 * 16]) : 0.f;
    float wh[32];
#pragma unroll
    for (int i = 0; i < 32; ++i) wh[i] = __ldg(&wp[(size_t)(NKP1 + chunk * 32 + i) * 16]);
    unsigned wk2[64];
    {
        const float* wkp = W_key + (size_t)(qq * 128) * NK + k0 + kl;
#pragma unroll
        for (int i = 0; i < 64; ++i) {
            float w0 = __ldg(&wkp[(size_t)(2 * i) * NK]);
            float w1 = __ldg(&wkp[(size_t)(2 * i + 1) * NK]);
            __half2 h2 = __floats2half2_rn(w0, w1);
            wk2[i] = *(unsigned*)&h2;
        }
    }
    const float wg0 = __ldg(&W_g[tid]), wg1 = __ldg(&W_g[tid + 256]);
    const float bgr = __ldg(&b_g[0]);
    const float bk  = (tid < 64) ? __ldg(&b_key[k0 + tid]) : 0.f;
    const int c0 = tid >> 5, c1 = (tid + 256) >> 5;
    const float bl0 = __ldg(&b_lstm[(c0 >> 2) * NH + j0 + (c0 & 3)]);
    const float bl1 = __ldg(&b_lstm[(c1 >> 2) * NH + j0 + (c1 & 3)]);

    for (int t = 0; t < NT; ++t) {
        // ==== S0: wait key_r(t-1) exchange =================================
        if (t > 0) bar_wait(2u * t);
        const float wcv = (kq == 0) ? __ldg(&g_wc[b2 * NT + t]) : 0.f;
        // ==== S1: issue key_r staging (covered by WhB below) ===============
        {
            const float4* s1 = (const float4*)g_keyrT;
            float4* d1 = (float4*)sAct;
            for (int i = tid; i < 2056; i += 256) cp_async16(d1 + i, s1 + i);
            asm volatile("cp.async.commit_group;" ::: "memory");
        }
        // ==== S2: WhB — all 32 rows, batch-groups 4..7 (slab already in) ===
        if (t > 0) {
            unsigned long long accH[8];
#pragma unroll
            for (int i = 0; i < 8; i++) accH[i] = 0ull;
#pragma unroll
            for (int i = 0; i < 32; ++i) {
                unsigned long long w2;
                asm("mov.b64 %0, {%1, %1};" : "=l"(w2) : "r"(__float_as_uint(wh[i])));
                const ulonglong2* a4 = (const ulonglong2*)(sAct + (NKP1 + chunk * 32 + i) * 32);
#pragma unroll
                for (int q = 0; q < 4; ++q) {
                    ulonglong2 aa = a4[(q + 4 + qrot) & 7];
                    fma2(accH[2 * q],     aa.x, w2);
                    fma2(accH[2 * q + 1], aa.y, w2);
                }
            }
#pragma unroll
            for (int q = 0; q < 4; ++q) {
                int bb = ((q + 4 + qrot) & 7) * 4;
                float f0, f1, f2, f3;
                asm("mov.b64 {%0, %1}, %2;" : "=f"(f0), "=f"(f1) : "l"(accH[2 * q]));
                asm("mov.b64 {%0, %1}, %2;" : "=f"(f2), "=f"(f3) : "l"(accH[2 * q + 1]));
                red[(bb + 0) * 273 + cl * 17 + chunk] = f0;
                red[(bb + 1) * 273 + cl * 17 + chunk] = f1;
                red[(bb + 2) * 273 + cl * 17 + chunk] = f2;
                red[(bb + 3) * 273 + cl * 17 + chunk] = f3;
            }
        }
        __syncthreads();
        // ==== S3: reduce Wh partials -> zbufH ==============================
        if (t > 0) {
            for (int o = tid; o < 512; o += 256) {
                int c = o >> 5, b = o & 31;
                const float* rr = &red[b * 273 + c * 17];
                float s = 0.f;
#pragma unroll
                for (int ch = 0; ch < 16; ++ch) s += rr[ch];
                zbufH[c * 33 + b] = s;
            }
        } else {
            for (int i = tid; i < SM_ZBUF; i += 256) zbufH[i] = 0.f;
        }
        asm volatile("cp.async.wait_group 0;" ::: "memory");
        __syncthreads();
        // ==== S4: W_x GEMM =================================================
        unsigned long long acc2[16];
#pragma unroll
        for (int i = 0; i < 16; i++) acc2[i] = 0ull;
#pragma unroll
        for (int i = 0; i < 16; ++i) {
            unsigned long long w2;
            asm("mov.b64 %0, {%1, %1};" : "=l"(w2) : "r"(__float_as_uint(wx[i])));
            const ulonglong2* a4 = (const ulonglong2*)(sAct + (chunk * 16 + i) * 32);
#pragma unroll
            for (int q = 0; q < 8; ++q) {
                ulonglong2 aa = a4[(q + qrot) & 7];
                fma2(acc2[2 * q],     aa.x, w2);
                fma2(acc2[2 * q + 1], aa.y, w2);
            }
        }
        if (chunk == 15) {
            unsigned long long w2;
            asm("mov.b64 %0, {%1, %1};" : "=l"(w2) : "r"(__float_as_uint(wxe)));
            const ulonglong2* a4 = (const ulonglong2*)(sAct + 256 * 32);
#pragma unroll
            for (int q = 0; q < 8; ++q) {
                ulonglong2 aa = a4[(q + qrot) & 7];
                fma2(acc2[2 * q],     aa.x, w2);
                fma2(acc2[2 * q + 1], aa.y, w2);
            }
        }
#pragma unroll
        for (int q = 0; q < 8; ++q) {
            int bb = ((q + qrot) & 7) * 4;
            float f0, f1, f2, f3;
            asm("mov.b64 {%0, %1}, %2;" : "=f"(f0), "=f"(f1) : "l"(acc2[2 * q]));
            asm("mov.b64 {%0, %1}, %2;" : "=f"(f2), "=f"(f3) : "l"(acc2[2 * q + 1]));
            red[(bb + 0) * 273 + cl * 17 + chunk] = f0;
            red[(bb + 1) * 273 + cl * 17 + chunk] = f1;
            red[(bb + 2) * 273 + cl * 17 + chunk] = f2;
            red[(bb + 3) * 273 + cl * 17 + chunk] = f3;
        }
        __syncthreads();
        { // combine: Wx partials + carried Wh + bias (preloaded)
            int b = tid & 31;
            const float* rr = &red[b * 273 + c0 * 17];
            float s = 0.f;
#pragma unroll
            for (int ch = 0; ch < 16; ++ch) s += rr[ch];
            zbuf[c0 * 33 + b] = s + zbufH[c0 * 33 + b] + bl0;
            rr = &red[b * 273 + c1 * 17];
            s = 0.f;
#pragma unroll
            for (int ch = 0; ch < 16; ++ch) s += rr[ch];
            zbuf[c1 * 33 + b] = s + zbufH[c1 * 33 + b] + bl1;
        }
        __syncthreads();
        // ==== S5: gates; c-state register-resident =========================
        if (tid < 128) {
            int jj = tid >> 5, b = tid & 31;
            float zi = zbuf[(0 + jj) * 33 + b];
            float zf = zbuf[(4 + jj) * 33 + b];
            float zc = zbuf[(8 + jj) * 33 + b];
            float zo = zbuf[(12 + jj) * 33 + b];
            float ig = sigmf(zi), fg = sigmf(zf);
            float gc = tanhfast(zc), og = sigmf(zo);
            creg = fg * creg + ig * gc;
            float hv = og * tanhfast(creg);
            int j = j0 + jj;
            if (t == NT - 1) {
                out[b * NH + j] = hv;
            } else {
                __stcg(&g_hT[j * NB + b], hv);
                __stcg(&g_hB[b * NH + j], hv);
            }
        }
        if (t == NT - 1) break;
        bar_arrive(2u * t + 1u);
        // ==== S7: attention partials (CTA-local) fill bar1 gap =============
        {
            float ax0 = 0.f, ay0 = 0.f, ax1 = 0.f, ay1 = 0.f;
            const __half2* mk2 = ((const __half2*)sMk) + kp;
            int t2 = q8;
            for (; t2 + 8 < t; t2 += 16) {
                float w0 = sWrow[t2], w1 = sWrow[t2 + 8];
                float2 m0 = __half22float2(mk2[t2 * 32]);
                float2 m1 = __half22float2(mk2[(t2 + 8) * 32]);
                ax0 += w0 * m0.x; ay0 += w0 * m0.y;
                ax1 += w1 * m1.x; ay1 += w1 * m1.y;
            }
            for (; t2 < t; t2 += 8) {
                float w0 = sWrow[t2];
                float2 m0 = __half22float2(mk2[t2 * 32]);
                ax0 += w0 * m0.x; ay0 += w0 * m0.y;
            }
            redk[384 + (kp * 8 + q8) * 2]     = ax0 + ax1;
            redk[384 + (kp * 8 + q8) * 2 + 1] = ay0 + ay1;
        }
        bar_wait(2u * t + 1u);
        // ==== S9: async loads: hB | S row t+1 | per-chunk h slab ===========
        if (tid < 128)
            cp_async16(((float4*)sh) + tid,
                       ((const float4*)(g_hB + (size_t)b2 * NH)) + tid);
        asm volatile("cp.async.commit_group;" ::: "memory");
        if (tid < 128)
            cp_async16(((float4*)sWrow) + tid,
                       ((const float4*)&g_S[((size_t)b2 * NT + t + 1) * NT]) + tid);
        asm volatile("cp.async.commit_group;" ::: "memory");
        {
            // each half-warp (chunk) loads ONLY its own 4 KB slab (rows
            // chunk*32..+31 of hT) -> per-thread wait_group covers exactly
            // what this chunk's Wh GEMM reads; no CTA-wide wait needed.
            const float4* s2 = ((const float4*)g_hT) + chunk * 256;
            float4* d2 = ((float4*)sAct) + 2056 + chunk * 256;
#pragma unroll
            for (int k = 0; k < 16; ++k)
                cp_async16(d2 + k * 16 + cl, s2 + k * 16 + cl);
            asm volatile("cp.async.commit_group;" ::: "memory");
        }
        // combine attention partials into registers while loads fly
        float attns = 0.f;
        if (tid < 64) {
            int kpp = tid >> 1, parr = tid & 1;
#pragma unroll
            for (int q = 0; q < 8; ++q) attns += redk[384 + (kpp * 8 + q) * 2 + parr];
        }
        asm volatile("cp.async.wait_group 2;" ::: "memory");  // hB done
        __syncthreads();
        // ==== S10: g, key_w, sMk[t], key_r — single sync ===================
        float pg = sh[tid] * wg0 + sh[tid + 256] * wg1;
#pragma unroll
        for (int o = 16; o; o >>= 1) pg += __shfl_xor_sync(~0u, pg, o);
        if ((tid & 31) == 0) redk[328 + (tid >> 5)] = pg;
        float ka[4] = {0.f, 0.f, 0.f, 0.f};
        {
            const float4* shq4 = (const float4*)(sh + qq * 128);
#pragma unroll
            for (int i = 0; i < 32; ++i) {
                float4 h4 = shq4[i];
                float2 f0 = __half22float2(*(__half2*)&wk2[2 * i]);
                float2 f1 = __half22float2(*(__half2*)&wk2[2 * i + 1]);
                ka[0] += h4.x * f0.x;
                ka[1] += h4.y * f0.y;
                ka[2] += h4.z * f1.x;
                ka[3] += h4.w * f1.y;
            }
        }
        redk[kl * 5 + qq] = (ka[0] + ka[1]) + (ka[2] + ka[3]);
        __syncthreads();
        float gv = 0.f;
        if (tid < 96) {
            float gs = ((redk[328] + redk[329]) + (redk[330] + redk[331]))
                     + ((redk[332] + redk[333]) + (redk[334] + redk[335]));
            gv = sigmf(gs + bgr);
        }
        if (tid < 64) {
            float kw = redk[tid * 5] + redk[tid * 5 + 1] + redk[tid * 5 + 2]
                     + redk[tid * 5 + 3] + bk;
            sMk[t * 64 + tid] = __float2half_rn(kw);
            float kr = (t > 0) ? gv * attns : 0.f;
            __stcg(&g_keyrT[(k0 + tid) * NB + b2], kr);
        }
        if (tid == 64 && kq == 0) {
            float kr = (t > 0) ? gv * wcv : 0.f;
            __stcg(&g_keyrT[NK * NB + b2], kr);
        }
        bar_arrive(2u * t + 2u);
        // ==== S12: WhA — per-thread slab wait, warp-local sync only ========
        asm volatile("cp.async.wait_group 0;" ::: "memory");
        __syncwarp();
        {
            unsigned long long accH[8];
#pragma unroll
            for (int i = 0; i < 8; i++) accH[i] = 0ull;
#pragma unroll
            for (int i = 0; i < 32; ++i) {
                unsigned long long w2;
                asm("mov.b64 %0, {%1, %1};" : "=l"(w2) : "r"(__float_as_uint(wh[i])));
                const ulonglong2* a4 = (const ulonglong2*)(sAct + (NKP1 + chunk * 32 + i) * 32);
#pragma unroll
                for (int q = 0; q < 4; ++q) {
                    ulonglong2 aa = a4[(q + qrot) & 7];
                    fma2(accH[2 * q],     aa.x, w2);
                    fma2(accH[2 * q + 1], aa.y, w2);
                }
            }
#pragma unroll
            for (int q = 0; q < 4; ++q) {
                int bb = ((q + qrot) & 7) * 4;
                float f0, f1, f2, f3;
                asm("mov.b64 {%0, %1}, %2;" : "=f"(f0), "=f"(f1) : "l"(accH[2 * q]));
                asm("mov.b64 {%0, %1}, %2;" : "=f"(f2), "=f"(f3) : "l"(accH[2 * q + 1]));
                red[(bb + 0) * 273 + cl * 17 + chunk] = f0;
                red[(bb + 1) * 273 + cl * 17 + chunk] = f1;
                red[(bb + 2) * 273 + cl * 17 + chunk] = f2;
                red[(bb + 3) * 273 + cl * 17 + chunk] = f3;
            }
        }
        // batch-groups 4..7 computed at next iteration's S2 (covers key_r load)
    }
}

// ---------------- launch ---------------------------------------------------
extern "C" void kernel_launch(void* const* d_in, const int* in_sizes, int n_in,
                              void* d_out, int out_size) {
    const float* x      = (const float*)d_in[0];
    const float* W_x    = (const float*)d_in[1];
    const float* W_h    = (const float*)d_in[2];
    const float* b_lstm = (const float*)d_in[3];
    const float* W_key  = (const float*)d_in[4];
    const float* b_key  = (const float*)d_in[5];
    const float* W_g    = (const float*)d_in[6];
    const float* b_g    = (const float*)d_in[7];
    float* out = (float*)d_out;

    cudaFuncSetAttribute(k_rec, cudaFuncAttributeMaxDynamicSharedMemorySize,
                         SM_FLOATS * (int)sizeof(float));

    k_pack<<<(NPACK + 255) / 256, 256>>>(W_x, W_h);
    k_gram<<<NB * 36, 256>>>(x);
    k_softmax<<<NB * NT, 128>>>((const float*)d_in[8], (const float*)d_in[9]);
    k_rec<<<NCTA, 256, SM_FLOATS * (int)sizeof(float)>>>(b_lstm, W_key, b_key, W_g, b_g, out);
}